// round 2
// baseline (speedup 1.0000x reference)
#include <cuda_runtime.h>
#include <math.h>

// Problem constants
#define NP     2048     // particles
#define NR     128      // rays
#define NS     256      // ray steps
#define MAPW   1024
#define MAPH   1024
#define ND     256      // sensor table dim
#define OCC_THRESH 0.97f

// Scratch (no cudaMalloc allowed)
__device__ float        g_pred[NP * 3];        // predicted particles
__device__ float        g_logl[NP];            // per-particle log likelihood
__device__ float        g_logits[NP];          // log_weights + log_l
__device__ unsigned     g_bitmap[MAPW * MAPH / 32];   // 128 KB occupancy bitmap
__device__ int          g_perm[NR];            // rays sorted by angle

// ---------------------------------------------------------------------------
// Kernel 0a: build occupancy bitmap.  1M threads, one bit each, ballot-packed.
// ---------------------------------------------------------------------------
__global__ __launch_bounds__(256) void kernBitmap(const float* __restrict__ map_grid)
{
    const int tid = blockIdx.x * blockDim.x + threadIdx.x;   // 0 .. 1M-1
    const bool occ = map_grid[tid] > OCC_THRESH;
    const unsigned mask = __ballot_sync(0xffffffffu, occ);
    if ((tid & 31) == 0) g_bitmap[tid >> 5] = mask;
}

// ---------------------------------------------------------------------------
// Kernel 0b: rank-sort the 128 ray angles (stable).  perm[rank] = ray index.
// ---------------------------------------------------------------------------
__global__ __launch_bounds__(NR) void kernSort(const float* __restrict__ obs_angles)
{
    __shared__ float s_a[NR];
    const int i = threadIdx.x;
    s_a[i] = obs_angles[i];
    __syncthreads();
    const float a = s_a[i];
    int rank = 0;
    #pragma unroll 8
    for (int j = 0; j < NR; j++) {
        float b = s_a[j];
        rank += (b < a) || (b == a && j < i);
    }
    g_perm[rank] = i;
}

// ---------------------------------------------------------------------------
// Kernel A: one block per particle, one thread per (angle-sorted) ray.
// Motion update + bitmap ray march (early exit) + sensor gather + reduce.
// ---------------------------------------------------------------------------
__global__ __launch_bounds__(128) void kernA(
    const float* __restrict__ particles,
    const float* __restrict__ log_weights,
    const float* __restrict__ obs_angles,
    const float* __restrict__ obs_dists,
    const float* __restrict__ sensor_table,
    const float* __restrict__ twist,
    const float* __restrict__ motion_noise)
{
    const int p = blockIdx.x;
    const int r = threadIdx.x;
    const int ray = g_perm[r];

    // Motion update (mul then add, no FMA contraction — match XLA elementwise)
    float x  = __fadd_rn(__fadd_rn(particles[p*3+0], twist[0]),
                         __fmul_rn(motion_noise[p*3+0], 0.5f));
    float y  = __fadd_rn(__fadd_rn(particles[p*3+1], twist[1]),
                         __fmul_rn(motion_noise[p*3+1], 0.5f));
    float th = __fadd_rn(__fadd_rn(particles[p*3+2], twist[2]),
                         __fmul_rn(motion_noise[p*3+2], 0.02f));

    if (r < 3) {
        g_pred[p*3 + r] = (r == 0) ? x : ((r == 1) ? y : th);
    }

    const float ang = __fadd_rn(th, obs_angles[ray]);
    const float c = cosf(ang);
    const float s = sinf(ang);

    int ebin = 255;   // no-hit: dist = 256 -> clip(int(256),0,255) = 255
    bool done = false;
    for (int base = 0; base < NS; base += 8) {
        unsigned h[8];
        #pragma unroll
        for (int j = 0; j < 8; j++) {
            float tf = (float)(base + j + 1);      // t = (k+1)*STEP, STEP=1
            float px = __fadd_rn(x, __fmul_rn(tf, c));
            float py = __fadd_rn(y, __fmul_rn(tf, s));
            int ix = __float2int_rz(px);
            int iy = __float2int_rz(py);
            ix = min(max(ix, 0), MAPW - 1);
            iy = min(max(iy, 0), MAPH - 1);
            unsigned w = __ldg(&g_bitmap[(iy << 5) + (ix >> 5)]);
            h[j] = (w >> (ix & 31)) & 1u;
        }
        #pragma unroll
        for (int j = 0; j < 8; j++) {
            if (h[j]) {
                int t = base + j + 1;
                ebin = min(t, 255);
                done = true;
                break;
            }
        }
        if (done) break;
    }

    // bin_w = MAX_DIST/D = 1.0 exactly, so o_bin = clip(int(obs_dist),0,255)
    int ob = __float2int_rz(obs_dists[ray]);
    ob = min(max(ob, 0), ND - 1);

    float val = __ldg(&sensor_table[ebin * ND + ob]);

    // Deterministic tree reduction over 128 threads (4 warps)
    __shared__ float s_part[4];
    #pragma unroll
    for (int o = 16; o > 0; o >>= 1)
        val += __shfl_down_sync(0xffffffffu, val, o);
    if ((r & 31) == 0) s_part[r >> 5] = val;
    __syncthreads();
    if (r == 0) {
        float ll = ((s_part[0] + s_part[1]) + s_part[2]) + s_part[3];
        g_logl[p] = ll;
        g_logits[p] = __fadd_rn(log_weights[p], __fmul_rn(1.0f, ll));
    }
}

// ---------------------------------------------------------------------------
// Kernel B: single block, 1024 threads.  Fused reductions, fast scan,
// systematic resampling, output assembly.  Thread t owns elements 2t, 2t+1.
// ---------------------------------------------------------------------------
__global__ __launch_bounds__(1024) void kernB(
    const float* __restrict__ noise_after,
    const float* __restrict__ resample_u,
    float* __restrict__ out)
{
    __shared__ float s_cum[NP];
    __shared__ float s_red[32 * 7];    // per-warp partials for fused reductions
    __shared__ float s_tot[8];         // broadcast totals
    __shared__ float s_wsum[32];       // warp totals for the scan

    const int tid  = threadIdx.x;
    const int lane = tid & 31;
    const int wrp  = tid >> 5;
    const int e0 = 2 * tid, e1 = 2 * tid + 1;

    // ---- max of logits (fused: warp reduce -> warp0 reduce) ----
    float l0 = g_logits[e0];
    float l1 = g_logits[e1];
    float m = fmaxf(l0, l1);
    #pragma unroll
    for (int o = 16; o > 0; o >>= 1)
        m = fmaxf(m, __shfl_xor_sync(0xffffffffu, m, o));
    if (lane == 0) s_red[wrp] = m;
    __syncthreads();
    if (wrp == 0) {
        float v = s_red[lane];
        #pragma unroll
        for (int o = 16; o > 0; o >>= 1)
            v = fmaxf(v, __shfl_xor_sync(0xffffffffu, v, o));
        if (lane == 0) s_tot[7] = v;
    }
    __syncthreads();
    const float mx = s_tot[7];
    const float mx10 = __fmul_rn(mx, 10.0f);

    // ---- exp terms + 7 fused weighted partial sums ----
    float acc[7] = {0.f, 0.f, 0.f, 0.f, 0.f, 0.f, 0.f};
    float e1v[2];
    #pragma unroll
    for (int k = 0; k < 2; k++) {
        const int i = (k == 0) ? e0 : e1;
        const float l = (k == 0) ? l0 : l1;
        // match jax: x = logits*10 (rounded mul), then x - max(x), then exp
        float w10 = expf(__fsub_rn(__fmul_rn(l, 10.0f), mx10));
        float w1  = expf(__fsub_rn(l, mx));
        float px  = g_pred[i*3+0];
        float py  = g_pred[i*3+1];
        float pth = g_pred[i*3+2];
        acc[0] += w10;              // S10
        acc[1] += w10 * px;         // Sx
        acc[2] += w10 * py;         // Sy
        acc[3] += w10 * sinf(pth);  // Ssin
        acc[4] += w10 * cosf(pth);  // Scos
        acc[5] += w1;               // S1
        acc[6] += w1 * g_logl[i];   // Sconf
        e1v[k] = w1;
    }
    #pragma unroll
    for (int q = 0; q < 7; q++) {
        float v = acc[q];
        #pragma unroll
        for (int o = 16; o > 0; o >>= 1)
            v += __shfl_xor_sync(0xffffffffu, v, o);
        if (lane == 0) s_red[q * 32 + wrp] = v;
    }
    __syncthreads();
    if (wrp == 0) {
        #pragma unroll
        for (int q = 0; q < 7; q++) {
            float v = s_red[q * 32 + lane];
            #pragma unroll
            for (int o = 16; o > 0; o >>= 1)
                v += __shfl_xor_sync(0xffffffffu, v, o);
            if (lane == 0) s_tot[q] = v;
        }
    }
    __syncthreads();
    const float S1 = s_tot[5];

    // ---- normalized weights + inclusive scan (warp scan + warp totals) ----
    float w0 = e1v[0] / S1;
    float w1n = e1v[1] / S1;
    float pairsum = w0 + w1n;
    float sc = pairsum;
    #pragma unroll
    for (int o = 1; o < 32; o <<= 1) {
        float v = __shfl_up_sync(0xffffffffu, sc, o);
        if (lane >= o) sc += v;
    }
    if (lane == 31) s_wsum[wrp] = sc;       // warp total
    __syncthreads();
    if (wrp == 0) {
        float v = s_wsum[lane];
        #pragma unroll
        for (int o = 1; o < 32; o <<= 1) {
            float u2 = __shfl_up_sync(0xffffffffu, v, o);
            if (lane >= o) v += u2;
        }
        s_wsum[lane] = v;                   // inclusive warp-total prefix
    }
    __syncthreads();
    float base = (wrp > 0) ? s_wsum[wrp - 1] : 0.f;
    float excl = base + (sc - pairsum);     // exclusive prefix of this pair
    s_cum[e0] = excl + w0;
    s_cum[e1] = excl + w0 + w1n;
    __syncthreads();

    // ---- systematic resampling: idx = searchsorted(cum, (i+u)/P), left ----
    const float u = resample_u[0];
    #pragma unroll
    for (int k = 0; k < 2; k++) {
        const int i = (k == 0) ? e0 : e1;
        float pos = __fdiv_rn(__fadd_rn((float)i, u), (float)NP);
        int lo = 0, hi = NP;
        while (lo < hi) {
            int mid = (lo + hi) >> 1;
            if (s_cum[mid] < pos) lo = mid + 1;
            else hi = mid;
        }
        int idx = min(lo, NP - 1);
        // new_p = p[idx] + noise_after * SIGMA_NOISE, SIGMA_NOISE=(0.2,0.2,0.01)
        out[3 + i*3 + 0] = __fadd_rn(g_pred[idx*3+0], __fmul_rn(noise_after[i*3+0], 0.2f));
        out[3 + i*3 + 1] = __fadd_rn(g_pred[idx*3+1], __fmul_rn(noise_after[i*3+1], 0.2f));
        out[3 + i*3 + 2] = __fadd_rn(g_pred[idx*3+2], __fmul_rn(noise_after[i*3+2], 0.01f));
    }

    if (tid == 0) {
        const float S10 = s_tot[0];
        out[0] = s_tot[1] / S10;
        out[1] = s_tot[2] / S10;
        out[2] = atan2f(s_tot[3] / S10, s_tot[4] / S10);
        out[3 + NP * 3] = s_tot[6] / S1;   // confidence, last element
    }
}

// ---------------------------------------------------------------------------
// Launch
// ---------------------------------------------------------------------------
extern "C" void kernel_launch(void* const* d_in, const int* in_sizes, int n_in,
                              void* d_out, int out_size)
{
    const float* particles    = (const float*)d_in[0];
    const float* log_weights  = (const float*)d_in[1];
    const float* obs_angles   = (const float*)d_in[2];
    const float* obs_dists    = (const float*)d_in[3];
    const float* map_grid     = (const float*)d_in[4];
    const float* sensor_table = (const float*)d_in[5];
    const float* twist        = (const float*)d_in[6];
    const float* motion_noise = (const float*)d_in[7];
    const float* resample_u   = (const float*)d_in[8];
    const float* noise_after  = (const float*)d_in[9];
    float* out = (float*)d_out;

    kernBitmap<<<(MAPW * MAPH) / 256, 256>>>(map_grid);
    kernSort<<<1, NR>>>(obs_angles);
    kernA<<<NP, 128>>>(particles, log_weights, obs_angles, obs_dists,
                       sensor_table, twist, motion_noise);
    kernB<<<1, 1024>>>(noise_after, resample_u, out);
}

// round 3
// speedup vs baseline: 1.4295x; 1.4295x over previous
#include <cuda_runtime.h>
#include <math.h>

// Problem constants
#define NP     2048     // particles
#define NR     128      // rays
#define NS     256      // ray steps
#define MAPW   1024
#define MAPH   1024
#define ND     256      // sensor table dim
#define OCC_THRESH 0.97f

// Window of the map that can ever be sampled: [128, 896) in both x and y.
// Particles are at 512 +/- ~85 worst case, rays reach <= 256, so samples lie in
// [~175, ~850] -- comfortably inside. Fallback path handles anything outside.
#define WIN0    128
#define WROWS   768
#define WWORDS  24          // 768/32 words per row
#define WIN_U32 (WROWS * WWORDS)   // 18432 words = 72 KB

#define PPB 7               // particles per block
#define TPB (PPB * 128)     // 896 threads
#define GRID ((NP + PPB - 1) / PPB)   // 293

// Scratch (no cudaMalloc allowed)
__device__ float    g_pred[NP * 3];     // predicted particles
__device__ float    g_trig[NP * 2];     // sin(th), cos(th)
__device__ float    g_logl[NP];         // per-particle log likelihood
__device__ float    g_logits[NP];       // log_weights + log_l
__device__ __align__(16) unsigned g_bitmap[MAPW * MAPH / 32];  // 128 KB occupancy bits
__device__ int      g_perm[NR];         // rays sorted by angle

// ---------------------------------------------------------------------------
// Kernel 0a: build occupancy bitmap.  1M threads, one bit each, ballot-packed.
// ---------------------------------------------------------------------------
__global__ __launch_bounds__(256) void kernBitmap(const float* __restrict__ map_grid)
{
    const int tid = blockIdx.x * blockDim.x + threadIdx.x;   // 0 .. 1M-1
    const bool occ = map_grid[tid] > OCC_THRESH;
    const unsigned mask = __ballot_sync(0xffffffffu, occ);
    if ((tid & 31) == 0) g_bitmap[tid >> 5] = mask;
}

// ---------------------------------------------------------------------------
// Kernel 0b: rank-sort the 128 ray angles (stable).  perm[rank] = ray index.
// ---------------------------------------------------------------------------
__global__ __launch_bounds__(NR) void kernSort(const float* __restrict__ obs_angles)
{
    __shared__ float s_a[NR];
    const int i = threadIdx.x;
    s_a[i] = obs_angles[i];
    __syncthreads();
    const float a = s_a[i];
    int rank = 0;
    #pragma unroll 8
    for (int j = 0; j < NR; j++) {
        float b = s_a[j];
        rank += (b < a) || (b == a && j < i);
    }
    g_perm[rank] = i;
}

// ---------------------------------------------------------------------------
// Kernel A: 7 particles per block, 128 threads per particle (one per ray,
// angle-sorted for divergence/locality).  Bitmap window cached in smem.
// Per-ray results stored by ORIGINAL ray index and reduced in the exact
// order of the round-1 kernel (bit-identical log_l).
// ---------------------------------------------------------------------------
__global__ __launch_bounds__(TPB, 2) void kernA(
    const float* __restrict__ particles,
    const float* __restrict__ log_weights,
    const float* __restrict__ obs_angles,
    const float* __restrict__ obs_dists,
    const float* __restrict__ sensor_table,
    const float* __restrict__ twist,
    const float* __restrict__ motion_noise)
{
    extern __shared__ unsigned smw[];
    unsigned* sm_bm  = smw;                               // 18432 u32
    float*    s_val  = (float*)(smw + WIN_U32);           // PPB*128 floats
    float*    s_part = s_val + PPB * 128;                 // PPB*4 floats

    const int tid = threadIdx.x;

    // ---- load bitmap window into smem (6 uint4 per row, 4608 total) ----
    {
        const uint4* gb4 = (const uint4*)g_bitmap;        // 8 uint4 per map row
        uint4* sb4 = (uint4*)sm_bm;                       // 6 uint4 per window row
        #pragma unroll
        for (int i = tid; i < WROWS * 6; i += TPB) {
            int row = i / 6;
            int j   = i - row * 6;
            sb4[i] = __ldg(&gb4[(row + WIN0) * 8 + 1 + j]);
        }
    }

    const int pi = tid >> 7;          // particle within block
    const int r  = tid & 127;         // sorted-rank ray slot
    const int p  = blockIdx.x * PPB + pi;
    const bool active = (p < NP);

    float x = 0.f, y = 0.f, th = 0.f, c = 0.f, s = 0.f;
    int ray = 0;
    if (active) {
        ray = g_perm[r];
        // Motion update (mul then add, no FMA contraction)
        x  = __fadd_rn(__fadd_rn(particles[p*3+0], twist[0]),
                       __fmul_rn(motion_noise[p*3+0], 0.5f));
        y  = __fadd_rn(__fadd_rn(particles[p*3+1], twist[1]),
                       __fmul_rn(motion_noise[p*3+1], 0.5f));
        th = __fadd_rn(__fadd_rn(particles[p*3+2], twist[2]),
                       __fmul_rn(motion_noise[p*3+2], 0.02f));
        if (r < 3) g_pred[p*3 + r] = (r == 0) ? x : ((r == 1) ? y : th);
        if (r == 3) g_trig[p*2 + 0] = sinf(th);
        if (r == 4) g_trig[p*2 + 1] = cosf(th);

        const float ang = __fadd_rn(th, obs_angles[ray]);
        c = cosf(ang);
        s = sinf(ang);
    }

    __syncthreads();   // smem bitmap ready

    float val = 0.f;
    if (active) {
        // Whole segment t in [1,256] inside window?  (segment is convex)
        float ex0 = __fadd_rn(x, c), ex1 = __fadd_rn(x, __fmul_rn(256.f, c));
        float ey0 = __fadd_rn(y, s), ey1 = __fadd_rn(y, __fmul_rn(256.f, s));
        float xmn = fminf(ex0, ex1), xmx = fmaxf(ex0, ex1);
        float ymn = fminf(ey0, ey1), ymx = fmaxf(ey0, ey1);
        const bool inw = (xmn >= (float)(WIN0 + 2)) && (xmx < (float)(WIN0 + WROWS - 2)) &&
                         (ymn >= (float)(WIN0 + 2)) && (ymx < (float)(WIN0 + WROWS - 2));

        int ebin = 255;   // no-hit: dist=256 -> clip(int(256),0,255)=255
        bool done = false;
        if (inw) {
            // Fast path: smem bitmap, no clamping needed (coords in-window).
            for (int base = 0; base < NS && !done; base += 8) {
                unsigned h[8];
                #pragma unroll
                for (int j = 0; j < 8; j++) {
                    float tf = (float)(base + j + 1);
                    float px = __fadd_rn(x, __fmul_rn(tf, c));
                    float py = __fadd_rn(y, __fmul_rn(tf, s));
                    int ix = __float2int_rz(px);
                    int iy = __float2int_rz(py);
                    unsigned w = sm_bm[(iy - WIN0) * WWORDS + (ix >> 5) - (WIN0 >> 5)];
                    h[j] = (w >> (ix & 31)) & 1u;
                }
                #pragma unroll
                for (int j = 0; j < 8; j++) {
                    if (h[j]) { ebin = min(base + j + 1, 255); done = true; break; }
                }
            }
        } else {
            // Fallback: global bitmap with full clamping (never taken for this input)
            for (int base = 0; base < NS && !done; base += 8) {
                unsigned h[8];
                #pragma unroll
                for (int j = 0; j < 8; j++) {
                    float tf = (float)(base + j + 1);
                    float px = __fadd_rn(x, __fmul_rn(tf, c));
                    float py = __fadd_rn(y, __fmul_rn(tf, s));
                    int ix = min(max(__float2int_rz(px), 0), MAPW - 1);
                    int iy = min(max(__float2int_rz(py), 0), MAPH - 1);
                    unsigned w = __ldg(&g_bitmap[(iy << 5) + (ix >> 5)]);
                    h[j] = (w >> (ix & 31)) & 1u;
                }
                #pragma unroll
                for (int j = 0; j < 8; j++) {
                    if (h[j]) { ebin = min(base + j + 1, 255); done = true; break; }
                }
            }
        }

        // bin_w = 1.0 exactly: o_bin = clip(int(obs_dist),0,255)
        int ob = min(max(__float2int_rz(obs_dists[ray]), 0), ND - 1);
        val = __ldg(&sensor_table[ebin * ND + ob]);

        s_val[pi * 128 + ray] = val;     // store by ORIGINAL ray index
    }
    __syncthreads();

    // Reduce in the exact round-1 order: thread slot r <- ray r.
    if (active) {
        float v = s_val[pi * 128 + r];
        #pragma unroll
        for (int o = 16; o > 0; o >>= 1)
            v += __shfl_down_sync(0xffffffffu, v, o);
        if ((r & 31) == 0) s_part[pi * 4 + (r >> 5)] = v;
    }
    __syncthreads();
    if (active && r == 0) {
        float ll = ((s_part[pi*4+0] + s_part[pi*4+1]) + s_part[pi*4+2]) + s_part[pi*4+3];
        g_logl[p] = ll;
        g_logits[p] = __fadd_rn(log_weights[p], __fmul_rn(1.0f, ll));
    }
}

// ---------------------------------------------------------------------------
// Kernel B: single block, 1024 threads.  EXACT round-1 arithmetic/order
// (7 sequential block reductions + Kogge-Stone scan); trig precomputed.
// ---------------------------------------------------------------------------
__device__ __forceinline__ float blockReduceSum(float v, float* s_red) {
    #pragma unroll
    for (int o = 16; o > 0; o >>= 1)
        v += __shfl_down_sync(0xffffffffu, v, o);
    int w = threadIdx.x >> 5, l = threadIdx.x & 31;
    if (l == 0) s_red[w] = v;
    __syncthreads();
    if (w == 0) {
        v = s_red[l];
        #pragma unroll
        for (int o = 16; o > 0; o >>= 1)
            v += __shfl_down_sync(0xffffffffu, v, o);
        if (l == 0) s_red[0] = v;
    }
    __syncthreads();
    float res = s_red[0];
    __syncthreads();
    return res;
}

__device__ __forceinline__ float blockReduceMax(float v, float* s_red) {
    #pragma unroll
    for (int o = 16; o > 0; o >>= 1)
        v = fmaxf(v, __shfl_down_sync(0xffffffffu, v, o));
    int w = threadIdx.x >> 5, l = threadIdx.x & 31;
    if (l == 0) s_red[w] = v;
    __syncthreads();
    if (w == 0) {
        v = s_red[l];
        #pragma unroll
        for (int o = 16; o > 0; o >>= 1)
            v = fmaxf(v, __shfl_down_sync(0xffffffffu, v, o));
        if (l == 0) s_red[0] = v;
    }
    __syncthreads();
    float res = s_red[0];
    __syncthreads();
    return res;
}

__global__ __launch_bounds__(1024) void kernB(
    const float* __restrict__ noise_after,
    const float* __restrict__ resample_u,
    float* __restrict__ out)
{
    __shared__ float s_cum[NP];
    __shared__ float s_red[32];

    const int tid = threadIdx.x;
    const int i0 = tid, i1 = tid + 1024;

    // --- max of logits ---
    float l0 = g_logits[i0];
    float l1 = g_logits[i1];
    float mx = blockReduceMax(fmaxf(l0, l1), s_red);
    float mx10 = __fmul_rn(mx, 10.0f);

    // --- exp terms + fused weighted partial sums ---
    float S10 = 0.f, Sx = 0.f, Sy = 0.f, Ssin = 0.f, Scos = 0.f;
    float S1 = 0.f, Sconf = 0.f;
    #pragma unroll
    for (int k = 0; k < 2; k++) {
        int i = (k == 0) ? i0 : i1;
        float l = (k == 0) ? l0 : l1;
        float e10 = expf(__fsub_rn(__fmul_rn(l, 10.0f), mx10));
        float e1  = expf(__fsub_rn(l, mx));
        float px = g_pred[i*3+0];
        float py = g_pred[i*3+1];
        S10  += e10;
        Sx   += e10 * px;
        Sy   += e10 * py;
        Ssin += e10 * g_trig[i*2+0];   // == e10 * sinf(pth), same bits
        Scos += e10 * g_trig[i*2+1];   // == e10 * cosf(pth), same bits
        S1   += e1;
        Sconf += e1 * g_logl[i];
        s_cum[i] = e1;
    }
    S10   = blockReduceSum(S10, s_red);
    Sx    = blockReduceSum(Sx, s_red);
    Sy    = blockReduceSum(Sy, s_red);
    Ssin  = blockReduceSum(Ssin, s_red);
    Scos  = blockReduceSum(Scos, s_red);
    S1    = blockReduceSum(S1, s_red);
    Sconf = blockReduceSum(Sconf, s_red);

    // --- normalize weights, inclusive Kogge-Stone scan (round-1 order) ---
    s_cum[i0] = s_cum[i0] / S1;
    s_cum[i1] = s_cum[i1] / S1;
    __syncthreads();

    for (int stride = 1; stride < NP; stride <<= 1) {
        float a0 = (i0 >= stride) ? s_cum[i0 - stride] : 0.f;
        float a1 = (i1 >= stride) ? s_cum[i1 - stride] : 0.f;
        __syncthreads();
        if (i0 >= stride) s_cum[i0] += a0;
        if (i1 >= stride) s_cum[i1] += a1;
        __syncthreads();
    }

    // --- systematic resampling: idx = searchsorted(cum, (i+u)/P), left ----
    const float u = resample_u[0];
    #pragma unroll
    for (int k = 0; k < 2; k++) {
        int i = (k == 0) ? i0 : i1;
        float pos = __fdiv_rn(__fadd_rn((float)i, u), (float)NP);
        int lo = 0, hi = NP;
        while (lo < hi) {
            int mid = (lo + hi) >> 1;
            if (s_cum[mid] < pos) lo = mid + 1;
            else hi = mid;
        }
        int idx = min(lo, NP - 1);
        out[3 + i*3 + 0] = __fadd_rn(g_pred[idx*3+0], __fmul_rn(noise_after[i*3+0], 0.2f));
        out[3 + i*3 + 1] = __fadd_rn(g_pred[idx*3+1], __fmul_rn(noise_after[i*3+1], 0.2f));
        out[3 + i*3 + 2] = __fadd_rn(g_pred[idx*3+2], __fmul_rn(noise_after[i*3+2], 0.01f));
    }

    if (tid == 0) {
        out[0] = Sx / S10;
        out[1] = Sy / S10;
        out[2] = atan2f(Ssin / S10, Scos / S10);
        out[3 + NP * 3] = Sconf / S1;   // confidence, last element
    }
}

// ---------------------------------------------------------------------------
// Launch
// ---------------------------------------------------------------------------
extern "C" void kernel_launch(void* const* d_in, const int* in_sizes, int n_in,
                              void* d_out, int out_size)
{
    const float* particles    = (const float*)d_in[0];
    const float* log_weights  = (const float*)d_in[1];
    const float* obs_angles   = (const float*)d_in[2];
    const float* obs_dists    = (const float*)d_in[3];
    const float* map_grid     = (const float*)d_in[4];
    const float* sensor_table = (const float*)d_in[5];
    const float* twist        = (const float*)d_in[6];
    const float* motion_noise = (const float*)d_in[7];
    const float* resample_u   = (const float*)d_in[8];
    const float* noise_after  = (const float*)d_in[9];
    float* out = (float*)d_out;

    // Dynamic smem: bitmap window + per-ray values + partials
    const int smemA = WIN_U32 * 4 + PPB * 128 * 4 + PPB * 4 * 4;   // 77,424 B
    // Opt-in above 48 KB (idempotent host-side call; not a stream op, safe
    // under graph capture).
    cudaFuncSetAttribute(kernA, cudaFuncAttributeMaxDynamicSharedMemorySize, smemA);

    kernBitmap<<<(MAPW * MAPH) / 256, 256>>>(map_grid);
    kernSort<<<1, NR>>>(obs_angles);
    kernA<<<GRID, TPB, smemA>>>(particles, log_weights, obs_angles, obs_dists,
                                sensor_table, twist, motion_noise);
    kernB<<<1, 1024>>>(noise_after, resample_u, out);
}

// round 4
// speedup vs baseline: 1.9863x; 1.3896x over previous
#include <cuda_runtime.h>
#include <math.h>

// Problem constants
#define NP     2048     // particles
#define NR     128      // rays
#define NS     256      // ray steps
#define MAPW   1024
#define MAPH   1024
#define ND     256      // sensor table dim
#define OCC_THRESH 0.97f

// Map window that can ever be sampled: [128, 896) in both x and y.
#define WIN0    128
#define WROWS   768
#define WWORDS  24           // 768/32 useful words per row
#define WPAD    25           // padded row stride (odd -> conflict-free smem banks)
#define WIN_U32 (WROWS * WPAD)

#define PPB 7                // particles per block
#define TPB (PPB * 128)      // 896 threads
#define GRID ((NP + PPB - 1) / PPB)   // 293

// Scratch (no cudaMalloc allowed)
__device__ float    g_pred[NP * 3];     // predicted particles
__device__ float    g_trig[NP * 2];     // sin(th), cos(th)
__device__ float    g_logl[NP];         // per-particle log likelihood
__device__ float    g_logits[NP];       // log_weights + log_l
__device__ __align__(16) unsigned g_bitmap[MAPW * MAPH / 32];  // 128 KB occupancy bits
__device__ int      g_perm[NR];         // rays sorted by angle

// ---------------------------------------------------------------------------
// Setup kernel: blocks 0..4095 build the occupancy bitmap (1 bit/cell,
// ballot-packed); block 4096 rank-sorts the 128 ray angles.
// ---------------------------------------------------------------------------
__global__ __launch_bounds__(256) void kernSetup(
    const float* __restrict__ map_grid,
    const float* __restrict__ obs_angles)
{
    if (blockIdx.x < (MAPW * MAPH) / 256) {
        const int tid = blockIdx.x * 256 + threadIdx.x;   // 0 .. 1M-1
        const bool occ = map_grid[tid] > OCC_THRESH;
        const unsigned mask = __ballot_sync(0xffffffffu, occ);
        if ((tid & 31) == 0) g_bitmap[tid >> 5] = mask;
    } else {
        __shared__ float s_a[NR];
        const int i = threadIdx.x;
        if (i < NR) s_a[i] = obs_angles[i];
        __syncthreads();
        if (i < NR) {
            const float a = s_a[i];
            int rank = 0;
            #pragma unroll 8
            for (int j = 0; j < NR; j++) {
                float b = s_a[j];
                rank += (b < a) || (b == a && j < i);
            }
            g_perm[rank] = i;
        }
    }
}

// ---------------------------------------------------------------------------
// Kernel A: 7 particles/block; each particle owns 4 warps; each warp serially
// processes 32 (angle-sorted) rays, marching 32 steps per iteration with all
// lanes + ballot first-hit.  Bitmap window cached in padded smem.
// Per-ray values stored by ORIGINAL ray index; reduction in exact R1 order.
// ---------------------------------------------------------------------------
__global__ __launch_bounds__(TPB, 2) void kernA(
    const float* __restrict__ particles,
    const float* __restrict__ log_weights,
    const float* __restrict__ obs_angles,
    const float* __restrict__ obs_dists,
    const float* __restrict__ sensor_table,
    const float* __restrict__ twist,
    const float* __restrict__ motion_noise)
{
    extern __shared__ unsigned smw[];
    unsigned* sm_bm  = smw;                               // 768*25 u32 (padded)
    float*    s_val  = (float*)(smw + WIN_U32);           // PPB*128 floats
    float*    s_part = s_val + PPB * 128;                 // PPB*4 floats

    const int tid = threadIdx.x;

    // ---- load bitmap window into padded smem rows ----
    for (int i = tid; i < WROWS * WWORDS; i += TPB) {
        int row = i / WWORDS;
        int j   = i - row * WWORDS;
        sm_bm[row * WPAD + j] = __ldg(&g_bitmap[(row + WIN0) * 32 + (WIN0 >> 5) + j]);
    }

    const int pi   = tid >> 7;        // particle within block
    const int r    = tid & 127;       // sorted-rank ray slot
    const int lane = tid & 31;
    const int p    = blockIdx.x * PPB + pi;
    const bool active = (p < NP);     // uniform per warp (warps don't straddle particles)

    float x = 0.f, y = 0.f, th = 0.f, c = 0.f, s = 0.f;
    int ray = 0;
    bool my_inw = false;
    if (active) {
        ray = g_perm[r];
        // Motion update (mul then add, no FMA contraction)
        x  = __fadd_rn(__fadd_rn(particles[p*3+0], twist[0]),
                       __fmul_rn(motion_noise[p*3+0], 0.5f));
        y  = __fadd_rn(__fadd_rn(particles[p*3+1], twist[1]),
                       __fmul_rn(motion_noise[p*3+1], 0.5f));
        th = __fadd_rn(__fadd_rn(particles[p*3+2], twist[2]),
                       __fmul_rn(motion_noise[p*3+2], 0.02f));
        if (r < 3) g_pred[p*3 + r] = (r == 0) ? x : ((r == 1) ? y : th);
        if (r == 3) g_trig[p*2 + 0] = sinf(th);
        if (r == 4) g_trig[p*2 + 1] = cosf(th);

        const float ang = __fadd_rn(th, obs_angles[ray]);
        c = cosf(ang);
        s = sinf(ang);

        // In-window test for this ray's whole segment (t in [1,256], convex)
        float ex0 = __fadd_rn(x, c), ex1 = __fadd_rn(x, __fmul_rn(256.f, c));
        float ey0 = __fadd_rn(y, s), ey1 = __fadd_rn(y, __fmul_rn(256.f, s));
        float xmn = fminf(ex0, ex1), xmx = fmaxf(ex0, ex1);
        float ymn = fminf(ey0, ey1), ymx = fmaxf(ey0, ey1);
        my_inw = (xmn >= (float)(WIN0 + 2)) && (xmx < (float)(WIN0 + WROWS - 2)) &&
                 (ymn >= (float)(WIN0 + 2)) && (ymx < (float)(WIN0 + WROWS - 2));
    }

    __syncthreads();   // smem bitmap ready

    int my_ebin = 255;   // no-hit: dist=256 -> clip(int(256),0,255)=255
    if (active) {
        const unsigned inw_mask = __ballot_sync(0xffffffffu, my_inw);
        const float lanef = (float)(lane + 1);

        // Each warp handles its 32 sorted-slot rays one at a time; 32 lanes
        // probe 32 consecutive steps; ballot picks the first hit.
        #pragma unroll 1
        for (int rr = 0; rr < 32; rr++) {
            const float rc = __shfl_sync(0xffffffffu, c, rr);
            const float rs = __shfl_sync(0xffffffffu, s, rr);
            int ebin = 255;
            if ((inw_mask >> rr) & 1u) {
                // Fast path: padded smem window, no clamping needed.
                float tf = lanef;
                #pragma unroll 1
                for (int it = 0; it < 8; it++) {
                    float px = __fadd_rn(x, __fmul_rn(tf, rc));
                    float py = __fadd_rn(y, __fmul_rn(tf, rs));
                    int ix = __float2int_rz(px);
                    int iy = __float2int_rz(py);
                    unsigned w = sm_bm[(iy - WIN0) * WPAD + ((ix >> 5) - (WIN0 >> 5))];
                    unsigned m = __ballot_sync(0xffffffffu, (w >> (ix & 31)) & 1u);
                    if (m) { ebin = min(it * 32 + __ffs(m), 255); break; }
                    tf = __fadd_rn(tf, 32.0f);
                }
            } else {
                // Fallback: global bitmap, full clamping (never taken here).
                float tf = lanef;
                #pragma unroll 1
                for (int it = 0; it < 8; it++) {
                    float px = __fadd_rn(x, __fmul_rn(tf, rc));
                    float py = __fadd_rn(y, __fmul_rn(tf, rs));
                    int ix = min(max(__float2int_rz(px), 0), MAPW - 1);
                    int iy = min(max(__float2int_rz(py), 0), MAPH - 1);
                    unsigned w = __ldg(&g_bitmap[(iy << 5) + (ix >> 5)]);
                    unsigned m = __ballot_sync(0xffffffffu, (w >> (ix & 31)) & 1u);
                    if (m) { ebin = min(it * 32 + __ffs(m), 255); break; }
                    tf = __fadd_rn(tf, 32.0f);
                }
            }
            if (lane == rr) my_ebin = ebin;   // lane rr owns sorted slot w*32+rr
        }

        // bin_w = 1.0 exactly: o_bin = clip(int(obs_dist),0,255)
        int ob = min(max(__float2int_rz(obs_dists[ray]), 0), ND - 1);
        float val = __ldg(&sensor_table[my_ebin * ND + ob]);
        s_val[pi * 128 + ray] = val;          // store by ORIGINAL ray index
    }
    __syncthreads();

    // Reduce in the exact round-1 order: thread slot r <- ray r.
    if (active) {
        float v = s_val[pi * 128 + r];
        #pragma unroll
        for (int o = 16; o > 0; o >>= 1)
            v += __shfl_down_sync(0xffffffffu, v, o);
        if ((r & 31) == 0) s_part[pi * 4 + (r >> 5)] = v;
    }
    __syncthreads();
    if (active && r == 0) {
        float ll = ((s_part[pi*4+0] + s_part[pi*4+1]) + s_part[pi*4+2]) + s_part[pi*4+3];
        g_logl[p] = ll;
        g_logits[p] = __fadd_rn(log_weights[p], __fmul_rn(1.0f, ll));
    }
}

// ---------------------------------------------------------------------------
// Kernel B: single block, 1024 threads.  EXACT round-1 arithmetic/order.
// ---------------------------------------------------------------------------
__device__ __forceinline__ float blockReduceSum(float v, float* s_red) {
    #pragma unroll
    for (int o = 16; o > 0; o >>= 1)
        v += __shfl_down_sync(0xffffffffu, v, o);
    int w = threadIdx.x >> 5, l = threadIdx.x & 31;
    if (l == 0) s_red[w] = v;
    __syncthreads();
    if (w == 0) {
        v = s_red[l];
        #pragma unroll
        for (int o = 16; o > 0; o >>= 1)
            v += __shfl_down_sync(0xffffffffu, v, o);
        if (l == 0) s_red[0] = v;
    }
    __syncthreads();
    float res = s_red[0];
    __syncthreads();
    return res;
}

__device__ __forceinline__ float blockReduceMax(float v, float* s_red) {
    #pragma unroll
    for (int o = 16; o > 0; o >>= 1)
        v = fmaxf(v, __shfl_down_sync(0xffffffffu, v, o));
    int w = threadIdx.x >> 5, l = threadIdx.x & 31;
    if (l == 0) s_red[w] = v;
    __syncthreads();
    if (w == 0) {
        v = s_red[l];
        #pragma unroll
        for (int o = 16; o > 0; o >>= 1)
            v = fmaxf(v, __shfl_down_sync(0xffffffffu, v, o));
        if (l == 0) s_red[0] = v;
    }
    __syncthreads();
    float res = s_red[0];
    __syncthreads();
    return res;
}

__global__ __launch_bounds__(1024) void kernB(
    const float* __restrict__ noise_after,
    const float* __restrict__ resample_u,
    float* __restrict__ out)
{
    __shared__ float s_cum[NP];
    __shared__ float s_red[32];

    const int tid = threadIdx.x;
    const int i0 = tid, i1 = tid + 1024;

    // --- max of logits ---
    float l0 = g_logits[i0];
    float l1 = g_logits[i1];
    float mx = blockReduceMax(fmaxf(l0, l1), s_red);
    float mx10 = __fmul_rn(mx, 10.0f);

    // --- exp terms + fused weighted partial sums ---
    float S10 = 0.f, Sx = 0.f, Sy = 0.f, Ssin = 0.f, Scos = 0.f;
    float S1 = 0.f, Sconf = 0.f;
    #pragma unroll
    for (int k = 0; k < 2; k++) {
        int i = (k == 0) ? i0 : i1;
        float l = (k == 0) ? l0 : l1;
        float e10 = expf(__fsub_rn(__fmul_rn(l, 10.0f), mx10));
        float e1  = expf(__fsub_rn(l, mx));
        float px = g_pred[i*3+0];
        float py = g_pred[i*3+1];
        S10  += e10;
        Sx   += e10 * px;
        Sy   += e10 * py;
        Ssin += e10 * g_trig[i*2+0];   // == e10 * sinf(pth), same bits
        Scos += e10 * g_trig[i*2+1];   // == e10 * cosf(pth), same bits
        S1   += e1;
        Sconf += e1 * g_logl[i];
        s_cum[i] = e1;
    }
    S10   = blockReduceSum(S10, s_red);
    Sx    = blockReduceSum(Sx, s_red);
    Sy    = blockReduceSum(Sy, s_red);
    Ssin  = blockReduceSum(Ssin, s_red);
    Scos  = blockReduceSum(Scos, s_red);
    S1    = blockReduceSum(S1, s_red);
    Sconf = blockReduceSum(Sconf, s_red);

    // --- normalize weights, inclusive Kogge-Stone scan (round-1 order) ---
    s_cum[i0] = s_cum[i0] / S1;
    s_cum[i1] = s_cum[i1] / S1;
    __syncthreads();

    for (int stride = 1; stride < NP; stride <<= 1) {
        float a0 = (i0 >= stride) ? s_cum[i0 - stride] : 0.f;
        float a1 = (i1 >= stride) ? s_cum[i1 - stride] : 0.f;
        __syncthreads();
        if (i0 >= stride) s_cum[i0] += a0;
        if (i1 >= stride) s_cum[i1] += a1;
        __syncthreads();
    }

    // --- systematic resampling: idx = searchsorted(cum, (i+u)/P), left ----
    const float u = resample_u[0];
    #pragma unroll
    for (int k = 0; k < 2; k++) {
        int i = (k == 0) ? i0 : i1;
        float pos = __fdiv_rn(__fadd_rn((float)i, u), (float)NP);
        int lo = 0, hi = NP;
        while (lo < hi) {
            int mid = (lo + hi) >> 1;
            if (s_cum[mid] < pos) lo = mid + 1;
            else hi = mid;
        }
        int idx = min(lo, NP - 1);
        out[3 + i*3 + 0] = __fadd_rn(g_pred[idx*3+0], __fmul_rn(noise_after[i*3+0], 0.2f));
        out[3 + i*3 + 1] = __fadd_rn(g_pred[idx*3+1], __fmul_rn(noise_after[i*3+1], 0.2f));
        out[3 + i*3 + 2] = __fadd_rn(g_pred[idx*3+2], __fmul_rn(noise_after[i*3+2], 0.01f));
    }

    if (tid == 0) {
        out[0] = Sx / S10;
        out[1] = Sy / S10;
        out[2] = atan2f(Ssin / S10, Scos / S10);
        out[3 + NP * 3] = Sconf / S1;   // confidence, last element
    }
}

// ---------------------------------------------------------------------------
// Launch
// ---------------------------------------------------------------------------
extern "C" void kernel_launch(void* const* d_in, const int* in_sizes, int n_in,
                              void* d_out, int out_size)
{
    const float* particles    = (const float*)d_in[0];
    const float* log_weights  = (const float*)d_in[1];
    const float* obs_angles   = (const float*)d_in[2];
    const float* obs_dists    = (const float*)d_in[3];
    const float* map_grid     = (const float*)d_in[4];
    const float* sensor_table = (const float*)d_in[5];
    const float* twist        = (const float*)d_in[6];
    const float* motion_noise = (const float*)d_in[7];
    const float* resample_u   = (const float*)d_in[8];
    const float* noise_after  = (const float*)d_in[9];
    float* out = (float*)d_out;

    // Dynamic smem: padded bitmap window + per-ray values + partials
    const int smemA = WIN_U32 * 4 + PPB * 128 * 4 + PPB * 4 * 4;   // ~80.5 KB
    cudaFuncSetAttribute(kernA, cudaFuncAttributeMaxDynamicSharedMemorySize, smemA);

    kernSetup<<<(MAPW * MAPH) / 256 + 1, 256>>>(map_grid, obs_angles);
    kernA<<<GRID, TPB, smemA>>>(particles, log_weights, obs_angles, obs_dists,
                                sensor_table, twist, motion_noise);
    kernB<<<1, 1024>>>(noise_after, resample_u, out);
}

// round 5
// speedup vs baseline: 1.9880x; 1.0009x over previous
#include <cuda_runtime.h>
#include <math.h>

// Problem constants
#define NP     2048     // particles
#define NR     128      // rays
#define NS     256      // ray steps
#define MAPW   1024
#define MAPH   1024
#define ND     256      // sensor table dim
#define OCC_THRESH 0.97f

// Map window that can ever be sampled (particles ~N(512,20^2) +-3.6 sigma,
// rays reach <=256.5):  y in [176, 848), x words 5..26  (x in [160, 864)).
#define WINY0   176
#define WROWS   672
#define WINXW0  5            // first x bitmap word
#define WWORDS  22           // x words per row (covers x in [160,864))
#define WPAD    23           // padded row stride, odd -> conflict-free banks
#define WIN_U32 (WROWS * WPAD)

#define PPB 7                // particles per block
#define TPB (PPB * 128)      // 896 threads
#define GRID ((NP + PPB - 1) / PPB)   // 293

// Scratch (no cudaMalloc allowed)
__device__ float    g_pred[NP * 3];     // predicted particles
__device__ float    g_trig[NP * 2];     // sin(th), cos(th)
__device__ float    g_logl[NP];         // per-particle log likelihood
__device__ float    g_logits[NP];       // log_weights + log_l
__device__ float    g_cum[NP];          // normalized-weight cumsum
__device__ __align__(16) unsigned g_bitmap[MAPW * MAPH / 32];  // 128 KB occupancy bits
__device__ int      g_perm[NR];         // rays sorted by angle

// ---------------------------------------------------------------------------
// Setup: blocks 0..1023 build the occupancy bitmap (float4 loads, 4 cells per
// thread, 8-lane OR-reduce packing -> MLP=4, coalesced).  Block 1024 rank-
// sorts the 128 ray angles.
// ---------------------------------------------------------------------------
__global__ __launch_bounds__(256) void kernSetup(
    const float* __restrict__ map_grid,
    const float* __restrict__ obs_angles)
{
    if (blockIdx.x < 1024) {
        const int t = blockIdx.x * 256 + threadIdx.x;     // 0 .. 262143
        const float4 v = __ldg(&((const float4*)map_grid)[t]);
        unsigned b = (v.x > OCC_THRESH ? 1u : 0u)
                   | (v.y > OCC_THRESH ? 2u : 0u)
                   | (v.z > OCC_THRESH ? 4u : 0u)
                   | (v.w > OCC_THRESH ? 8u : 0u);
        const int lane = threadIdx.x & 31;
        const int grp  = lane >> 3;                        // 8-lane group
        const unsigned gmask = 0xFFu << (grp * 8);
        unsigned word = __reduce_or_sync(gmask, b << ((lane & 7) * 4));
        if ((lane & 7) == 0) g_bitmap[t >> 3] = word;
    } else {
        __shared__ float s_a[NR];
        const int i = threadIdx.x;
        if (i < NR) s_a[i] = obs_angles[i];
        __syncthreads();
        if (i < NR) {
            const float a = s_a[i];
            int rank = 0;
            #pragma unroll 8
            for (int j = 0; j < NR; j++) {
                float b = s_a[j];
                rank += (b < a) || (b == a && j < i);
            }
            g_perm[rank] = i;
        }
    }
}

// ---------------------------------------------------------------------------
// Kernel A: 7 particles/block; each particle owns 4 warps; each warp serially
// processes 32 (angle-sorted) rays, marching 32 steps per iteration with all
// lanes + ballot first-hit.  Bitmap window cached in padded smem.
// Per-ray values stored by ORIGINAL ray index; reduction in exact R1 order.
// ---------------------------------------------------------------------------
__global__ __launch_bounds__(TPB, 2) void kernA(
    const float* __restrict__ particles,
    const float* __restrict__ log_weights,
    const float* __restrict__ obs_angles,
    const float* __restrict__ obs_dists,
    const float* __restrict__ sensor_table,
    const float* __restrict__ twist,
    const float* __restrict__ motion_noise)
{
    extern __shared__ unsigned smw[];
    unsigned* sm_bm  = smw;                               // WROWS*WPAD u32
    float*    s_val  = (float*)(smw + WIN_U32);           // PPB*128 floats
    float*    s_part = s_val + PPB * 128;                 // PPB*4 floats

    const int tid = threadIdx.x;

    // ---- load bitmap window into padded smem rows ----
    for (int i = tid; i < WROWS * WWORDS; i += TPB) {
        int row = i / WWORDS;
        int j   = i - row * WWORDS;
        sm_bm[row * WPAD + j] = __ldg(&g_bitmap[(row + WINY0) * 32 + WINXW0 + j]);
    }

    const int pi   = tid >> 7;        // particle within block
    const int r    = tid & 127;       // sorted-rank ray slot
    const int lane = tid & 31;
    const int p    = blockIdx.x * PPB + pi;
    const bool active = (p < NP);     // uniform per warp

    float x = 0.f, y = 0.f, th = 0.f, c = 0.f, s = 0.f;
    int ray = 0;
    bool my_inw = false;
    if (active) {
        ray = g_perm[r];
        // Motion update (mul then add, no FMA contraction)
        x  = __fadd_rn(__fadd_rn(particles[p*3+0], twist[0]),
                       __fmul_rn(motion_noise[p*3+0], 0.5f));
        y  = __fadd_rn(__fadd_rn(particles[p*3+1], twist[1]),
                       __fmul_rn(motion_noise[p*3+1], 0.5f));
        th = __fadd_rn(__fadd_rn(particles[p*3+2], twist[2]),
                       __fmul_rn(motion_noise[p*3+2], 0.02f));
        if (r < 3) g_pred[p*3 + r] = (r == 0) ? x : ((r == 1) ? y : th);
        if (r == 3) g_trig[p*2 + 0] = sinf(th);
        if (r == 4) g_trig[p*2 + 1] = cosf(th);

        const float ang = __fadd_rn(th, obs_angles[ray]);
        c = cosf(ang);
        s = sinf(ang);

        // In-window test for this ray's whole segment (t in [1,256], convex)
        float ex0 = __fadd_rn(x, c), ex1 = __fadd_rn(x, __fmul_rn(256.f, c));
        float ey0 = __fadd_rn(y, s), ey1 = __fadd_rn(y, __fmul_rn(256.f, s));
        float xmn = fminf(ex0, ex1), xmx = fmaxf(ex0, ex1);
        float ymn = fminf(ey0, ey1), ymx = fmaxf(ey0, ey1);
        my_inw = (xmn >= 162.f) && (xmx < 862.f) &&
                 (ymn >= (float)(WINY0 + 2)) && (ymx < (float)(WINY0 + WROWS - 2));
    }

    __syncthreads();   // smem bitmap ready

    int my_ebin = 255;   // no-hit: dist=256 -> clip(int(256),0,255)=255
    if (active) {
        const unsigned inw_mask = __ballot_sync(0xffffffffu, my_inw);
        const float lanef = (float)(lane + 1);

        #pragma unroll 1
        for (int rr = 0; rr < 32; rr++) {
            const float rc = __shfl_sync(0xffffffffu, c, rr);
            const float rs = __shfl_sync(0xffffffffu, s, rr);
            int ebin = 255;
            if ((inw_mask >> rr) & 1u) {
                // Fast path: padded smem window, no clamping needed.
                float tf = lanef;
                #pragma unroll 1
                for (int it = 0; it < 8; it++) {
                    float px = __fadd_rn(x, __fmul_rn(tf, rc));
                    float py = __fadd_rn(y, __fmul_rn(tf, rs));
                    int ix = __float2int_rz(px);
                    int iy = __float2int_rz(py);
                    unsigned w = sm_bm[(iy - WINY0) * WPAD + ((ix >> 5) - WINXW0)];
                    unsigned m = __ballot_sync(0xffffffffu, (w >> (ix & 31)) & 1u);
                    if (m) { ebin = min(it * 32 + __ffs(m), 255); break; }
                    tf = __fadd_rn(tf, 32.0f);
                }
            } else {
                // Fallback: global bitmap, full clamping (outliers only).
                float tf = lanef;
                #pragma unroll 1
                for (int it = 0; it < 8; it++) {
                    float px = __fadd_rn(x, __fmul_rn(tf, rc));
                    float py = __fadd_rn(y, __fmul_rn(tf, rs));
                    int ix = min(max(__float2int_rz(px), 0), MAPW - 1);
                    int iy = min(max(__float2int_rz(py), 0), MAPH - 1);
                    unsigned w = __ldg(&g_bitmap[(iy << 5) + (ix >> 5)]);
                    unsigned m = __ballot_sync(0xffffffffu, (w >> (ix & 31)) & 1u);
                    if (m) { ebin = min(it * 32 + __ffs(m), 255); break; }
                    tf = __fadd_rn(tf, 32.0f);
                }
            }
            my_ebin = (lane == rr) ? ebin : my_ebin;
        }

        // bin_w = 1.0 exactly: o_bin = clip(int(obs_dist),0,255)
        int ob = min(max(__float2int_rz(obs_dists[ray]), 0), ND - 1);
        float val = __ldg(&sensor_table[my_ebin * ND + ob]);
        s_val[pi * 128 + ray] = val;          // store by ORIGINAL ray index
    }
    __syncthreads();

    // Reduce in the exact round-1 order: thread slot r <- ray r.
    if (active) {
        float v = s_val[pi * 128 + r];
        #pragma unroll
        for (int o = 16; o > 0; o >>= 1)
            v += __shfl_down_sync(0xffffffffu, v, o);
        if ((r & 31) == 0) s_part[pi * 4 + (r >> 5)] = v;
    }
    __syncthreads();
    if (active && r == 0) {
        float ll = ((s_part[pi*4+0] + s_part[pi*4+1]) + s_part[pi*4+2]) + s_part[pi*4+3];
        g_logl[p] = ll;
        g_logits[p] = __fadd_rn(log_weights[p], __fmul_rn(1.0f, ll));
    }
}

// ---------------------------------------------------------------------------
// Kernel B1: single block, 1024 threads.  EXACT round-1 arithmetic/order for
// max, softmax sums, estimates, scan.  Writes cum to gmem for kernB2.
// ---------------------------------------------------------------------------
__device__ __forceinline__ float blockReduceSum(float v, float* s_red) {
    #pragma unroll
    for (int o = 16; o > 0; o >>= 1)
        v += __shfl_down_sync(0xffffffffu, v, o);
    int w = threadIdx.x >> 5, l = threadIdx.x & 31;
    if (l == 0) s_red[w] = v;
    __syncthreads();
    if (w == 0) {
        v = s_red[l];
        #pragma unroll
        for (int o = 16; o > 0; o >>= 1)
            v += __shfl_down_sync(0xffffffffu, v, o);
        if (l == 0) s_red[0] = v;
    }
    __syncthreads();
    float res = s_red[0];
    __syncthreads();
    return res;
}

__device__ __forceinline__ float blockReduceMax(float v, float* s_red) {
    #pragma unroll
    for (int o = 16; o > 0; o >>= 1)
        v = fmaxf(v, __shfl_down_sync(0xffffffffu, v, o));
    int w = threadIdx.x >> 5, l = threadIdx.x & 31;
    if (l == 0) s_red[w] = v;
    __syncthreads();
    if (w == 0) {
        v = s_red[l];
        #pragma unroll
        for (int o = 16; o > 0; o >>= 1)
            v = fmaxf(v, __shfl_down_sync(0xffffffffu, v, o));
        if (l == 0) s_red[0] = v;
    }
    __syncthreads();
    float res = s_red[0];
    __syncthreads();
    return res;
}

__global__ __launch_bounds__(1024) void kernB1(float* __restrict__ out)
{
    __shared__ float s_cum[NP];
    __shared__ float s_red[32];

    const int tid = threadIdx.x;
    const int i0 = tid, i1 = tid + 1024;

    // --- max of logits ---
    float l0 = g_logits[i0];
    float l1 = g_logits[i1];
    float mx = blockReduceMax(fmaxf(l0, l1), s_red);
    float mx10 = __fmul_rn(mx, 10.0f);

    // --- exp terms + fused weighted partial sums ---
    float S10 = 0.f, Sx = 0.f, Sy = 0.f, Ssin = 0.f, Scos = 0.f;
    float S1 = 0.f, Sconf = 0.f;
    #pragma unroll
    for (int k = 0; k < 2; k++) {
        int i = (k == 0) ? i0 : i1;
        float l = (k == 0) ? l0 : l1;
        float e10 = expf(__fsub_rn(__fmul_rn(l, 10.0f), mx10));
        float e1  = expf(__fsub_rn(l, mx));
        float px = g_pred[i*3+0];
        float py = g_pred[i*3+1];
        S10  += e10;
        Sx   += e10 * px;
        Sy   += e10 * py;
        Ssin += e10 * g_trig[i*2+0];   // == e10 * sinf(pth), same bits
        Scos += e10 * g_trig[i*2+1];   // == e10 * cosf(pth), same bits
        S1   += e1;
        Sconf += e1 * g_logl[i];
        s_cum[i] = e1;
    }
    S10   = blockReduceSum(S10, s_red);
    Sx    = blockReduceSum(Sx, s_red);
    Sy    = blockReduceSum(Sy, s_red);
    Ssin  = blockReduceSum(Ssin, s_red);
    Scos  = blockReduceSum(Scos, s_red);
    S1    = blockReduceSum(S1, s_red);
    Sconf = blockReduceSum(Sconf, s_red);

    // --- normalize weights, inclusive Kogge-Stone scan (round-1 order) ---
    s_cum[i0] = s_cum[i0] / S1;
    s_cum[i1] = s_cum[i1] / S1;
    __syncthreads();

    for (int stride = 1; stride < NP; stride <<= 1) {
        float a0 = (i0 >= stride) ? s_cum[i0 - stride] : 0.f;
        float a1 = (i1 >= stride) ? s_cum[i1 - stride] : 0.f;
        __syncthreads();
        if (i0 >= stride) s_cum[i0] += a0;
        if (i1 >= stride) s_cum[i1] += a1;
        __syncthreads();
    }

    g_cum[i0] = s_cum[i0];
    g_cum[i1] = s_cum[i1];

    if (tid == 0) {
        out[0] = Sx / S10;
        out[1] = Sy / S10;
        out[2] = atan2f(Ssin / S10, Scos / S10);
        out[3 + NP * 3] = Sconf / S1;   // confidence, last element
    }
}

// ---------------------------------------------------------------------------
// Kernel B2: 8 blocks x 256 threads.  Systematic resampling + gather + noise,
// fully parallel.  cum staged through smem; arithmetic identical to round 1.
// ---------------------------------------------------------------------------
__global__ __launch_bounds__(256) void kernB2(
    const float* __restrict__ noise_after,
    const float* __restrict__ resample_u,
    float* __restrict__ out)
{
    __shared__ float s_cum[NP];
    const int tid = threadIdx.x;
    #pragma unroll
    for (int k = 0; k < NP / 256; k++)
        s_cum[k * 256 + tid] = g_cum[k * 256 + tid];
    __syncthreads();

    const int i = blockIdx.x * 256 + tid;
    const float u = resample_u[0];
    float pos = __fdiv_rn(__fadd_rn((float)i, u), (float)NP);
    int lo = 0, hi = NP;
    while (lo < hi) {
        int mid = (lo + hi) >> 1;
        if (s_cum[mid] < pos) lo = mid + 1;
        else hi = mid;
    }
    int idx = min(lo, NP - 1);
    // new_p = p[idx] + noise_after * SIGMA_NOISE, SIGMA_NOISE=(0.2,0.2,0.01)
    out[3 + i*3 + 0] = __fadd_rn(g_pred[idx*3+0], __fmul_rn(noise_after[i*3+0], 0.2f));
    out[3 + i*3 + 1] = __fadd_rn(g_pred[idx*3+1], __fmul_rn(noise_after[i*3+1], 0.2f));
    out[3 + i*3 + 2] = __fadd_rn(g_pred[idx*3+2], __fmul_rn(noise_after[i*3+2], 0.01f));
}

// ---------------------------------------------------------------------------
// Launch
// ---------------------------------------------------------------------------
extern "C" void kernel_launch(void* const* d_in, const int* in_sizes, int n_in,
                              void* d_out, int out_size)
{
    const float* particles    = (const float*)d_in[0];
    const float* log_weights  = (const float*)d_in[1];
    const float* obs_angles   = (const float*)d_in[2];
    const float* obs_dists    = (const float*)d_in[3];
    const float* map_grid     = (const float*)d_in[4];
    const float* sensor_table = (const float*)d_in[5];
    const float* twist        = (const float*)d_in[6];
    const float* motion_noise = (const float*)d_in[7];
    const float* resample_u   = (const float*)d_in[8];
    const float* noise_after  = (const float*)d_in[9];
    float* out = (float*)d_out;

    // Dynamic smem: padded bitmap window + per-ray values + partials
    const int smemA = WIN_U32 * 4 + PPB * 128 * 4 + PPB * 4 * 4;   // ~65.5 KB
    cudaFuncSetAttribute(kernA, cudaFuncAttributeMaxDynamicSharedMemorySize, smemA);

    kernSetup<<<1025, 256>>>(map_grid, obs_angles);
    kernA<<<GRID, TPB, smemA>>>(particles, log_weights, obs_angles, obs_dists,
                                sensor_table, twist, motion_noise);
    kernB1<<<1, 1024>>>(out);
    kernB2<<<NP / 256, 256>>>(noise_after, resample_u, out);
}